// round 14
// baseline (speedup 1.0000x reference)
#include <cuda_runtime.h>
#include <math.h>
#include <stdint.h>

#define B_      2
#define T_      8192
#define D_      256
#define E_      8
#define TWO_D   512
#define N_TOK   16384
#define CAP     2048
#define NELEM   (N_TOK * TWO_D)   /* 8388608 */
#define NPAIR   (N_TOK * D_)      /* 4194304 */
#define TIE_CAP 2048
#define N_TILES 512               /* 8 experts x 16 bm x 4 bn */
#define GEMM_BLOCKS 304

// ---------------- scratch (device globals; no allocation allowed) ------------
__device__ float  g_x_states[NELEM];
__device__ float  g_x_target[NELEM];
__device__ float  g_x_eff[NELEM];
__device__ float  g_pred[NELEM];
__device__ float  g_scoresT[E_ * N_TOK];
__device__ int    g_idx[E_ * CAP];
__device__ float  g_vals[E_ * CAP];
__device__ float  g_counts[N_TOK];
__device__ double g_resnorm;
__device__ int    g_tile_ctr[12];

// ---------------- packed f32x2 helpers (sm_100-family safe) -------------------
#define FMA2(c, a, b) asm("fma.rn.f32x2 %0, %1, %2, %0;" : "+l"(c) : "l"(a), "l"(b))
#define MUL2(c, a, b) asm("mul.rn.f32x2 %0, %1, %2;" : "=l"(c) : "l"(a), "l"(b))
#define PACK2(d, x)   asm("mov.b64 %0, {%1, %1};" : "=l"(d) : "f"(x))
#define UNPACK2(lo, hi, p) asm("mov.b64 {%0, %1}, %2;" : "=f"(lo), "=f"(hi) : "l"(p))
__device__ __forceinline__ void red2(float* p, float lo, float hi) {
    asm volatile("red.global.add.v2.f32 [%0], {%1, %2};"
                 :: "l"(p), "f"(lo), "f"(hi) : "memory");
}

// ---------------- init: copy x -> x_states, compute phase targets ------------
__global__ void k_init(const float* __restrict__ x,
                       const float* __restrict__ cosp,
                       const float* __restrict__ sinp) {
    int i = blockIdx.x * blockDim.x + threadIdx.x;
    if (i == 0) {
        g_resnorm = 0.0;
#pragma unroll
        for (int s = 0; s < 12; s++) g_tile_ctr[s] = 0;
    }
    if (i >= NPAIR) return;
    int n = i >> 8;          // token index
    int d = i & 255;
    int t = n & (T_ - 1);
    const float2* x2 = (const float2*)x;
    float2 cur = x2[i];
    ((float2*)g_x_states)[i] = cur;
    float2 tg;
    if (t == 0) {
        tg = cur;
    } else {
        float2 p = x2[i - 256];          // (n-1, d)
        float c = cosp[d], s = sinp[d];
        tg.x = p.x * c - p.y * s;
        tg.y = p.x * s + p.y * c;
    }
    ((float2*)g_x_target)[i] = tg;
}

// ------------- fused: zero pred/counts + prime delays + gate + softmax -------
// 8 tokens per block (512 threads, 4 sequential pairs); gate_w loaded once.
// Gate reduction: 2 butterfly rounds + smem class-partials (fewer SHFLs).
__global__ void k_delays_gate(const float* __restrict__ dgains,
                              const float* __restrict__ gate_w) {
    __shared__ float s_gw[TWO_D * E_];   // 16 KB
    __shared__ float s_red[16 * 64];     // 16 warps x 8 classes x 8 experts
    int tid = threadIdx.x;
    int sub = tid >> 8;
    int d = tid & 255;
    int warp = tid >> 5, lane = tid & 31;

    // fused zeroing: 8 pred rows (1024 float4) + 8 counts
    ((float4*)g_pred)[(size_t)blockIdx.x * 1024 + tid]       = make_float4(0.f, 0.f, 0.f, 0.f);
    ((float4*)g_pred)[(size_t)blockIdx.x * 1024 + tid + 512] = make_float4(0.f, 0.f, 0.f, 0.f);
    if (tid < 8) g_counts[blockIdx.x * 8 + tid] = 0.f;

    for (int i = tid; i < TWO_D * E_; i += 512) s_gw[i] = gate_w[i];
    __syncthreads();

    const float2* xs2 = (const float2*)g_x_states;
    const int taus[4] = {1, 2, 3, 5};

    for (int p8 = 0; p8 < 4; p8++) {
        int n = blockIdx.x * 8 + p8 * 2 + sub;
        int t = n & (T_ - 1);
        float2 v = xs2[n * 256 + d];
#pragma unroll
        for (int q = 0; q < 4; q++) {
            int tau = taus[q];
            if (t >= tau) {
                float2 s = xs2[(n - tau) * 256 + d];
                float gr = dgains[(q * 256 + d) * 2 + 0];
                float gi = dgains[(q * 256 + d) * 2 + 1];
                v.x += s.x * gr - s.y * gi;
                v.y += s.x * gi + s.y * gr;
            }
        }
        ((float2*)g_x_eff)[n * 256 + d] = v;

        float p[E_];
#pragma unroll
        for (int e = 0; e < E_; e++)
            p[e] = v.x * s_gw[(2 * d) * E_ + e] + v.y * s_gw[(2 * d + 1) * E_ + e];

        // 2 butterfly rounds -> every lane holds class (lane&7) partials
#pragma unroll
        for (int e = 0; e < E_; e++) {
            p[e] += __shfl_xor_sync(0xffffffffu, p[e], 16);
            p[e] += __shfl_xor_sync(0xffffffffu, p[e], 8);
        }
        if (lane < 8)
#pragma unroll
            for (int e = 0; e < E_; e++) s_red[warp * 64 + lane * 8 + e] = p[e];
        __syncthreads();

        if (d < E_) {
            float logit = 0.f;
#pragma unroll
            for (int w = 0; w < 8; w++)
#pragma unroll
                for (int c = 0; c < 8; c++)
                    logit += s_red[(sub * 8 + w) * 64 + c * 8 + d];
            float m = logit;
#pragma unroll
            for (int o = 4; o > 0; o >>= 1)
                m = fmaxf(m, __shfl_xor_sync(0x000000ffu, m, o, 8));
            float ex = expf(logit - m);
            float s = ex;
#pragma unroll
            for (int o = 4; o > 0; o >>= 1)
                s += __shfl_xor_sync(0x000000ffu, s, o, 8);
            g_scoresT[d * N_TOK + n] = ex / s;
        }
        __syncthreads();   // s_red WAR before next pair
    }
}

// -------- per-expert top-CAP selection (radix select + unordered compact) ----
// 8 blocks (one per expert), 1024 threads, 64KB dynamic smem
__global__ void k_topk(int do_counts) {
    extern __shared__ unsigned u[];      // 16384 flipped keys
    __shared__ int      hist[256];
    __shared__ unsigned s_prefix;
    __shared__ int      s_K;
    __shared__ int      s_gcnt;
    __shared__ int      s_tcnt;
    __shared__ int      s_tlist[TIE_CAP];
    __shared__ int      base_ti;
    __shared__ int      wtot_ti[32];

    int e = blockIdx.x;
    int tid = threadIdx.x;
    int warp = tid >> 5, lane = tid & 31;
    const float* sc = g_scoresT + e * N_TOK;

    for (int i = tid; i < N_TOK; i += 1024) {
        unsigned v = __float_as_uint(sc[i]);
        v = (v & 0x80000000u) ? ~v : (v | 0x80000000u);
        u[i] = v;
    }
    if (tid == 0) {
        s_prefix = 0u; s_K = CAP;
        s_gcnt = 0; s_tcnt = 0; base_ti = 0;
    }
    __syncthreads();

    // radix select: find value of CAP-th largest key (4 byte levels)
    for (int level = 0; level < 4; level++) {
        int shift = 24 - 8 * level;
        unsigned hm = (level == 0) ? 0u : (0xFFFFFFFFu << (shift + 8));
        if (tid < 256) hist[tid] = 0;
        __syncthreads();
        unsigned pref = s_prefix;
        for (int i = tid; i < N_TOK; i += 1024) {
            unsigned v = u[i];
            if ((v & hm) == pref) atomicAdd(&hist[(v >> shift) & 255], 1);
        }
        __syncthreads();
        // warp 0: parallel descending-bucket selection
        if (warp == 0) {
            int cnt[8];
            int tsum = 0;
#pragma unroll
            for (int j = 0; j < 8; j++) {
                cnt[j] = hist[255 - (lane * 8 + j)];
                tsum += cnt[j];
            }
            int pre = tsum;
#pragma unroll
            for (int o = 1; o < 32; o <<= 1) {
                int vv = __shfl_up_sync(0xffffffffu, pre, o);
                if (lane >= o) pre += vv;
            }
            pre -= tsum;                      // exclusive prefix (higher buckets)
            int K = s_K;
            if (pre < K && K <= pre + tsum) {
                int c = pre;
#pragma unroll
                for (int j = 0; j < 8; j++) {
                    if (K <= c + cnt[j]) {
                        s_K = K - c;
                        s_prefix = pref | ((unsigned)(255 - (lane * 8 + j)) << shift);
                        break;
                    }
                    c += cnt[j];
                }
            }
        }
        __syncthreads();
    }
    unsigned thr = s_prefix;
    int ties_needed = s_K;              // radix invariant
    int cgt = CAP - ties_needed;        // count strictly greater

    // unordered compaction for >thr (warp-aggregated atomics, no block syncs);
    // ties gathered into a small list for rank selection.
    unsigned lmask = (1u << lane) - 1u;
#pragma unroll
    for (int ch = 0; ch < 16; ch++) {
        int i = ch * 1024 + tid;
        unsigned v = u[i];
        int fgt = (v > thr);
        int fti = (v == thr);
        unsigned bg = __ballot_sync(0xffffffffu, fgt);
        if (bg) {
            int base = 0;
            if (lane == 0) base = atomicAdd(&s_gcnt, __popc(bg));
            base = __shfl_sync(0xffffffffu, base, 0);
            if (fgt) {
                int pos = base + __popc(bg & lmask);
                g_idx[e * CAP + pos] = i;
                g_vals[e * CAP + pos] = sc[i];
                if (do_counts) atomicAdd(&g_counts[i], 1.0f);
            }
        }
        unsigned bt = __ballot_sync(0xffffffffu, fti);
        if (bt) {
            int tb = 0;
            if (lane == 0) tb = atomicAdd(&s_tcnt, __popc(bt));
            tb = __shfl_sync(0xffffffffu, tb, 0);
            if (fti) {
                int tp = tb + __popc(bt & lmask);
                if (tp < TIE_CAP) s_tlist[tp] = i;
            }
        }
    }
    __syncthreads();
    int cti = s_tcnt;

    if (cti == ties_needed) {
        for (int j = tid; j < cti; j += 1024) {
            int i = s_tlist[j];
            int pos = cgt + j;
            g_idx[e * CAP + pos] = i;
            g_vals[e * CAP + pos] = sc[i];
            if (do_counts) atomicAdd(&g_counts[i], 1.0f);
        }
    } else if (cti <= TIE_CAP) {
        // keep the lowest-index ties (matches lax.top_k tie-break)
        for (int j = tid; j < cti; j += 1024) {
            int ii = s_tlist[j];
            int rank = 0;
            for (int q = 0; q < cti; q++) rank += (s_tlist[q] < ii);
            if (rank < ties_needed) {
                int pos = cgt + rank;
                g_idx[e * CAP + pos] = ii;
                g_vals[e * CAP + pos] = sc[ii];
                if (do_counts) atomicAdd(&g_counts[ii], 1.0f);
            }
        }
    } else {
        // degenerate fallback: ordered ballot-scan over all ties
        for (int ch = 0; ch < 16; ch++) {
            int i = ch * 1024 + tid;
            int fti = (u[i] == thr);
            unsigned bt = __ballot_sync(0xffffffffu, fti);
            if (lane == 0) wtot_ti[warp] = __popc(bt);
            __syncthreads();
            if (tid == 0) {
                int at = base_ti;
                for (int w = 0; w < 32; w++) {
                    int tt = wtot_ti[w];
                    wtot_ti[w] = at;
                    at += tt;
                }
                base_ti = at;
            }
            __syncthreads();
            int pt = wtot_ti[warp] + __popc(bt & lmask);
            if (fti && pt < ties_needed) {
                int pos = cgt + pt;
                g_idx[e * CAP + pos] = i;
                g_vals[e * CAP + pos] = sc[i];
                if (do_counts) atomicAdd(&g_counts[i], 1.0f);
            }
            __syncthreads();
        }
    }
}

// ---------------- expert GEMM: persistent grid + double-buffered smem ---------
// 304 blocks, 256 threads; tiles: 512 = e(8) x bm(16) x bn(4); 128x128x16
// tile, 8x8 micro via fma.rn.f32x2, ONE barrier per K-chunk.
// Warp output footprint reshaped to 64 rows x 32 cols (2x4 warp grid): A LDS
// covers a contiguous 128B span (1 wavefront) and B LDS only 64B distinct
// (vs 256B before) -- cuts L1/crossbar wavefronts, the measured bottleneck.
__global__ void __launch_bounds__(256) k_gemm(const float* __restrict__ expert_w,
                                              int ctr_slot) {
    __shared__ __align__(16) float As[2][16][132];
    __shared__ __align__(16) float Bs[2][16][132];
    __shared__ int   s_rows[128];
    __shared__ float s_vals[128];
    __shared__ int   s_next;

    int tid = threadIdx.x;
    int warp = tid >> 5, lane = tid & 31;
    int wr = warp >> 2;              // 0..1   (64-row halves)
    int wc = warp & 3;               // 0..3   (32-col quarters)
    int lr = lane >> 2;              // 0..7   (4-row quads)
    int lc = lane & 3;               // 0..3   (4-col quads)
    int rbase = wr * 64 + lr * 4;    // thread rows: rbase+0..3, rbase+32..35
    int cbase = wc * 32 + lc * 4;    // thread cols: cbase+0..3, cbase+16..19

    int am = tid & 127;
    int ah = (tid >> 7) * 8;                    // 0 or 8
    int bc = (tid & 31) * 4;
    int bk = tid >> 5;

    while (true) {
        __syncthreads();      // protects s_next, s_rows/s_vals, smem reuse
        if (tid == 0) s_next = atomicAdd(&g_tile_ctr[ctr_slot], 1);
        __syncthreads();
        int tile = s_next;
        if (tile >= N_TILES) break;

        int e  = tile >> 6;
        int bm = (tile >> 2) & 15;
        int bn = tile & 3;

        if (tid < 128) {
            s_rows[tid] = g_idx[e * CAP + bm * 128 + tid];
            s_vals[tid] = g_vals[e * CAP + bm * 128 + tid];
        }
        __syncthreads();

        const float* W = expert_w + (size_t)e * TWO_D * TWO_D + bn * 128;
        size_t arow = (size_t)s_rows[am] * TWO_D;

        // prologue: chunk 0 -> buffer 0
        {
            float4 a0 = *(const float4*)&g_x_eff[arow + ah];
            float4 a1 = *(const float4*)&g_x_eff[arow + ah + 4];
            float4 b0 = *(const float4*)&W[(size_t)bk * TWO_D + bc];
            float4 b1 = *(const float4*)&W[(size_t)(bk + 8) * TWO_D + bc];
            As[0][ah + 0][am] = a0.x; As[0][ah + 1][am] = a0.y;
            As[0][ah + 2][am] = a0.z; As[0][ah + 3][am] = a0.w;
            As[0][ah + 4][am] = a1.x; As[0][ah + 5][am] = a1.y;
            As[0][ah + 6][am] = a1.z; As[0][ah + 7][am] = a1.w;
            *(float4*)&Bs[0][bk][bc]     = b0;
            *(float4*)&Bs[0][bk + 8][bc] = b1;
        }
        __syncthreads();

        unsigned long long acc[8][4];
#pragma unroll
        for (int i = 0; i < 8; i++)
#pragma unroll
            for (int j = 0; j < 4; j++) acc[i][j] = 0ull;

#pragma unroll 1
        for (int c = 0; c < 32; c++) {
            int cur = c & 1, nxt = cur ^ 1;
            float4 pa0, pa1, pb0, pb1;
            bool more = (c + 1 < 32);
            if (more) {
                int kn = (c + 1) * 16;
                pa0 = *(const float4*)&g_x_eff[arow + kn + ah];
                pa1 = *(const float4*)&g_x_eff[arow + kn + ah + 4];
                pb0 = *(const float4*)&W[(size_t)(kn + bk) * TWO_D + bc];
                pb1 = *(const float4*)&W[(size_t)(kn + bk + 8) * TWO_D + bc];
            }

#pragma unroll
            for (int kk = 0; kk < 16; kk++) {
                float4 a0 = *(const float4*)&As[cur][kk][rbase];
                float4 a1 = *(const float4*)&As[cur][kk][rbase + 32];
                ulonglong2 b0 = *(const ulonglong2*)&Bs[cur][kk][cbase];
                ulonglong2 b1 = *(const ulonglong2*)&Bs[cur][kk][cbase + 16];
                float av[8] = {a0.x, a0.y, a0.z, a0.w, a1.x, a1.y, a1.z, a1.w};
#pragma unroll
                for (int i = 0; i < 8; i++) {
                    unsigned long long ad;
                    PACK2(ad, av[i]);
                    FMA2(acc[i][0], ad, b0.x);
                    FMA2(acc[i][1], ad, b0.y);
                    FMA2(acc[i][2], ad, b1.x);
                    FMA2(acc[i][3], ad, b1.y);
                }
            }

            if (more) {
                As[nxt][ah + 0][am] = pa0.x; As[nxt][ah + 1][am] = pa0.y;
                As[nxt][ah + 2][am] = pa0.z; As[nxt][ah + 3][am] = pa0.w;
                As[nxt][ah + 4][am] = pa1.x; As[nxt][ah + 5][am] = pa1.y;
                As[nxt][ah + 6][am] = pa1.z; As[nxt][ah + 7][am] = pa1.w;
                *(float4*)&Bs[nxt][bk][bc]     = pb0;
                *(float4*)&Bs[nxt][bk + 8][bc] = pb1;
                __syncthreads();   // stores to nxt visible; cur free for overwrite
            }
        }

#pragma unroll
        for (int i = 0; i < 8; i++) {
            int m = rbase + (i & 3) + (i >> 2) * 32;
            int token = s_rows[m];
            unsigned long long vvd;
            PACK2(vvd, s_vals[m]);
            float* p = g_pred + (size_t)token * TWO_D + bn * 128;
#pragma unroll
            for (int jp = 0; jp < 4; jp++) {
                unsigned long long sc2;
                MUL2(sc2, acc[i][jp], vvd);
                float lo, hi;
                UNPACK2(lo, hi, sc2);
                int n = cbase + (jp & 1) * 2 + (jp >> 1) * 16;
                red2(&p[n], lo, hi);
            }
        }
    }
}

// ---------------- state update (float4) ---------------------------------------
__global__ void k_update(float lr) {
    int i = blockIdx.x * blockDim.x + threadIdx.x;
    if (i >= NELEM / 4) return;
    float4 t = ((const float4*)g_x_target)[i];
    float4 p = ((const float4*)g_pred)[i];
    float4 s = ((float4*)g_x_states)[i];
    s.x += lr * fminf(fmaxf(t.x - p.x, -10.f), 10.f);
    s.y += lr * fminf(fmaxf(t.y - p.y, -10.f), 10.f);
    s.z += lr * fminf(fmaxf(t.z - p.z, -10.f), 10.f);
    s.w += lr * fminf(fmaxf(t.w - p.w, -10.f), 10.f);
    ((float4*)g_x_states)[i] = s;
}

// ---------------- normalize + tanh activate (float4) ---------------------------
__global__ void k_activate(const float* __restrict__ act_bias) {
    int i = blockIdx.x * blockDim.x + threadIdx.x;
    if (i >= NELEM / 4) return;
    int n = i >> 7;            // 128 float4 per token row
    int q = i & 127;           // covers d = 2q, 2q+1
    float dn = fmaxf(g_counts[n], 1.0f);
    float inv = 1.0f / dn;
    float4 p = ((const float4*)g_pred)[i];
    float4 b = ((const float4*)act_bias)[q];
    float4 r;
    r.x = tanhf(p.x * inv + b.x);
    r.y = tanhf(p.y * inv + b.y);
    r.z = tanhf(p.z * inv + b.z);
    r.w = tanhf(p.w * inv + b.w);
    ((float4*)g_x_states)[i] = r;
}

// ---------------- final output + residual norm (float4) ------------------------
__global__ void k_output(float* __restrict__ out) {
    __shared__ double sd[256];
    int tid = threadIdx.x;
    int i = blockIdx.x * blockDim.x + tid;
    double sloc = 0.0;
    if (i < NELEM / 4) {
        float4 xs = ((const float4*)g_x_states)[i];
        float4 tg = ((const float4*)g_x_target)[i];
        float4 pg = ((const float4*)g_pred)[i];
        float4 o;
        o.x = xs.x + 0.5f * (tg.x - pg.x);
        o.y = xs.y + 0.5f * (tg.y - pg.y);
        o.z = xs.z + 0.5f * (tg.z - pg.z);
        o.w = xs.w + 0.5f * (tg.w - pg.w);
        ((float4*)out)[i] = o;
        float d0r = tg.x - pg.x, d0i = tg.y - pg.y;
        float d1r = tg.z - pg.z, d1i = tg.w - pg.w;
        sloc = (double)sqrtf(d0r * d0r + d0i * d0i) + (double)sqrtf(d1r * d1r + d1i * d1i);
    }
    sd[tid] = sloc;
    __syncthreads();
    for (int s = 128; s > 0; s >>= 1) {
        if (tid < s) sd[tid] += sd[tid + s];
        __syncthreads();
    }
    if (tid == 0) atomicAdd(&g_resnorm, sd[0]);
}

__global__ void k_final(float* __restrict__ out, int pos) {
    out[pos] = (float)(g_resnorm / (double)NPAIR);
}

// ---------------- host launcher -----------------------------------------------
extern "C" void kernel_launch(void* const* d_in, const int* in_sizes, int n_in,
                              void* d_out, int out_size) {
    const float* x        = (const float*)d_in[0];
    const float* dgains   = (const float*)d_in[1];
    const float* cosp     = (const float*)d_in[2];
    const float* sinp     = (const float*)d_in[3];
    const float* gate_w   = (const float*)d_in[4];
    const float* expert_w = (const float*)d_in[5];
    const float* act_bias = (const float*)d_in[6];
    float* out = (float*)d_out;

    cudaFuncSetAttribute(k_topk, cudaFuncAttributeMaxDynamicSharedMemorySize, 64 * 1024);

    const int EB = 256;

    k_init<<<(NPAIR + EB - 1) / EB, EB>>>(x, cosp, sinp);

    float lr = 0.5f;
    int slot = 0;
    for (int it = 0; it < 8; it++) {
        k_delays_gate<<<N_TOK / 8, 512>>>(dgains, gate_w);
        k_topk<<<E_, 1024, 64 * 1024>>>(it == 7 ? 1 : 0);
        k_gemm<<<GEMM_BLOCKS, 256>>>(expert_w, slot++);
        if (it < 7) {
            k_update<<<NELEM / 4 / EB, EB>>>(lr);
            lr *= 0.85f;
        }
    }

    k_activate<<<NELEM / 4 / EB, EB>>>(act_bias);

    // gradient pass
    k_delays_gate<<<N_TOK / 8, 512>>>(dgains, gate_w);
    k_topk<<<E_, 1024, 64 * 1024>>>(0);
    k_gemm<<<GEMM_BLOCKS, 256>>>(expert_w, slot++);

    k_output<<<NELEM / 4 / EB, EB>>>(out);
    k_final<<<1, 1>>>(out, out_size - 1);
}

// round 16
// speedup vs baseline: 1.3576x; 1.3576x over previous
#include <cuda_runtime.h>
#include <math.h>
#include <stdint.h>

#define B_      2
#define T_      8192
#define D_      256
#define E_      8
#define TWO_D   512
#define N_TOK   16384
#define CAP     2048
#define NELEM   (N_TOK * TWO_D)   /* 8388608 */
#define NPAIR   (N_TOK * D_)      /* 4194304 */
#define TIE_CAP 2048
#define N_TILES 512               /* 8 experts x 16 bm x 4 bn */
#define GEMM_BLOCKS 304

// ---------------- scratch (device globals; no allocation allowed) ------------
__device__ float  g_x_states[NELEM];
__device__ float  g_x_target[NELEM];
__device__ float  g_x_eff[NELEM];
__device__ float  g_pred[NELEM];
__device__ float  g_scoresT[E_ * N_TOK];
__device__ int    g_idx[E_ * CAP];
__device__ float  g_vals[E_ * CAP];
__device__ float  g_counts[N_TOK];
__device__ double g_resnorm;
__device__ int    g_tile_ctr[12];

// ---------------- packed f32x2 helpers (sm_100-family safe) -------------------
#define FMA2(c, a, b) asm("fma.rn.f32x2 %0, %1, %2, %0;" : "+l"(c) : "l"(a), "l"(b))
#define MUL2(c, a, b) asm("mul.rn.f32x2 %0, %1, %2;" : "=l"(c) : "l"(a), "l"(b))
#define PACK2(d, x)   asm("mov.b64 %0, {%1, %1};" : "=l"(d) : "f"(x))
#define UNPACK2(lo, hi, p) asm("mov.b64 {%0, %1}, %2;" : "=f"(lo), "=f"(hi) : "l"(p))
__device__ __forceinline__ void red2(float* p, float lo, float hi) {
    asm volatile("red.global.add.v2.f32 [%0], {%1, %2};"
                 :: "l"(p), "f"(lo), "f"(hi) : "memory");
}

// ---------------- init: copy x -> x_states, compute phase targets ------------
__global__ void k_init(const float* __restrict__ x,
                       const float* __restrict__ cosp,
                       const float* __restrict__ sinp) {
    int i = blockIdx.x * blockDim.x + threadIdx.x;
    if (i == 0) {
        g_resnorm = 0.0;
#pragma unroll
        for (int s = 0; s < 12; s++) g_tile_ctr[s] = 0;
    }
    if (i >= NPAIR) return;
    int n = i >> 8;          // token index
    int d = i & 255;
    int t = n & (T_ - 1);
    const float2* x2 = (const float2*)x;
    float2 cur = x2[i];
    ((float2*)g_x_states)[i] = cur;
    float2 tg;
    if (t == 0) {
        tg = cur;
    } else {
        float2 p = x2[i - 256];          // (n-1, d)
        float c = cosp[d], s = sinp[d];
        tg.x = p.x * c - p.y * s;
        tg.y = p.x * s + p.y * c;
    }
    ((float2*)g_x_target)[i] = tg;
}

// ------------- fused: zero pred/counts + prime delays + gate + softmax -------
// 8 tokens per block (512 threads, 4 sequential pairs); gate_w loaded once.
// Gate reduction: 2 butterfly rounds + smem class-partials (fewer SHFLs).
__global__ void k_delays_gate(const float* __restrict__ dgains,
                              const float* __restrict__ gate_w) {
    __shared__ float s_gw[TWO_D * E_];   // 16 KB
    __shared__ float s_red[16 * 64];     // 16 warps x 8 classes x 8 experts
    int tid = threadIdx.x;
    int sub = tid >> 8;
    int d = tid & 255;
    int warp = tid >> 5, lane = tid & 31;

    // fused zeroing: 8 pred rows (1024 float4) + 8 counts
    ((float4*)g_pred)[(size_t)blockIdx.x * 1024 + tid]       = make_float4(0.f, 0.f, 0.f, 0.f);
    ((float4*)g_pred)[(size_t)blockIdx.x * 1024 + tid + 512] = make_float4(0.f, 0.f, 0.f, 0.f);
    if (tid < 8) g_counts[blockIdx.x * 8 + tid] = 0.f;

    for (int i = tid; i < TWO_D * E_; i += 512) s_gw[i] = gate_w[i];
    __syncthreads();

    const float2* xs2 = (const float2*)g_x_states;
    const int taus[4] = {1, 2, 3, 5};

    for (int p8 = 0; p8 < 4; p8++) {
        int n = blockIdx.x * 8 + p8 * 2 + sub;
        int t = n & (T_ - 1);
        float2 v = xs2[n * 256 + d];
#pragma unroll
        for (int q = 0; q < 4; q++) {
            int tau = taus[q];
            if (t >= tau) {
                float2 s = xs2[(n - tau) * 256 + d];
                float gr = dgains[(q * 256 + d) * 2 + 0];
                float gi = dgains[(q * 256 + d) * 2 + 1];
                v.x += s.x * gr - s.y * gi;
                v.y += s.x * gi + s.y * gr;
            }
        }
        ((float2*)g_x_eff)[n * 256 + d] = v;

        float p[E_];
#pragma unroll
        for (int e = 0; e < E_; e++)
            p[e] = v.x * s_gw[(2 * d) * E_ + e] + v.y * s_gw[(2 * d + 1) * E_ + e];

        // 2 butterfly rounds -> every lane holds class (lane&7) partials
#pragma unroll
        for (int e = 0; e < E_; e++) {
            p[e] += __shfl_xor_sync(0xffffffffu, p[e], 16);
            p[e] += __shfl_xor_sync(0xffffffffu, p[e], 8);
        }
        if (lane < 8)
#pragma unroll
            for (int e = 0; e < E_; e++) s_red[warp * 64 + lane * 8 + e] = p[e];
        __syncthreads();

        if (d < E_) {
            float logit = 0.f;
#pragma unroll
            for (int w = 0; w < 8; w++)
#pragma unroll
                for (int c = 0; c < 8; c++)
                    logit += s_red[(sub * 8 + w) * 64 + c * 8 + d];
            float m = logit;
#pragma unroll
            for (int o = 4; o > 0; o >>= 1)
                m = fmaxf(m, __shfl_xor_sync(0x000000ffu, m, o, 8));
            float ex = expf(logit - m);
            float s = ex;
#pragma unroll
            for (int o = 4; o > 0; o >>= 1)
                s += __shfl_xor_sync(0x000000ffu, s, o, 8);
            g_scoresT[d * N_TOK + n] = ex / s;
        }
        __syncthreads();   // s_red WAR before next pair
    }
}

// -------- per-expert top-CAP selection (radix select + unordered compact) ----
// 8 blocks (one per expert), 1024 threads, 64KB dynamic smem.
// Level-0 histogram fused into the key-load loop (one fewer 16K sweep).
__global__ void k_topk(int do_counts) {
    extern __shared__ unsigned u[];      // 16384 flipped keys
    __shared__ int      hist[256];
    __shared__ unsigned s_prefix;
    __shared__ int      s_K;
    __shared__ int      s_gcnt;
    __shared__ int      s_tcnt;
    __shared__ int      s_tlist[TIE_CAP];
    __shared__ int      base_ti;
    __shared__ int      wtot_ti[32];

    int e = blockIdx.x;
    int tid = threadIdx.x;
    int warp = tid >> 5, lane = tid & 31;
    const float* sc = g_scoresT + e * N_TOK;

    if (tid < 256) hist[tid] = 0;
    if (tid == 0) {
        s_prefix = 0u; s_K = CAP;
        s_gcnt = 0; s_tcnt = 0; base_ti = 0;
    }
    __syncthreads();

    // load keys + level-0 histogram in one sweep
    for (int i = tid; i < N_TOK; i += 1024) {
        unsigned v = __float_as_uint(sc[i]);
        v = (v & 0x80000000u) ? ~v : (v | 0x80000000u);
        u[i] = v;
        atomicAdd(&hist[v >> 24], 1);
    }
    __syncthreads();

    // radix select: find value of CAP-th largest key (4 byte levels)
    for (int level = 0; level < 4; level++) {
        int shift = 24 - 8 * level;
        // warp 0: parallel descending-bucket selection on current histogram
        if (warp == 0) {
            int cnt[8];
            int tsum = 0;
#pragma unroll
            for (int j = 0; j < 8; j++) {
                cnt[j] = hist[255 - (lane * 8 + j)];
                tsum += cnt[j];
            }
            int pre = tsum;
#pragma unroll
            for (int o = 1; o < 32; o <<= 1) {
                int vv = __shfl_up_sync(0xffffffffu, pre, o);
                if (lane >= o) pre += vv;
            }
            pre -= tsum;                      // exclusive prefix (higher buckets)
            int K = s_K;
            if (pre < K && K <= pre + tsum) {
                int c = pre;
#pragma unroll
                for (int j = 0; j < 8; j++) {
                    if (K <= c + cnt[j]) {
                        s_K = K - c;
                        s_prefix = s_prefix |
                                   ((unsigned)(255 - (lane * 8 + j)) << shift);
                        break;
                    }
                    c += cnt[j];
                }
            }
        }
        __syncthreads();

        // build next level's histogram (skip after last level)
        if (level < 3) {
            int nshift = shift - 8;
            unsigned hm = 0xFFFFFFFFu << shift;
            if (tid < 256) hist[tid] = 0;
            __syncthreads();
            unsigned pref = s_prefix;
            for (int i = tid; i < N_TOK; i += 1024) {
                unsigned v = u[i];
                if ((v & hm) == pref) atomicAdd(&hist[(v >> nshift) & 255], 1);
            }
            __syncthreads();
        }
    }
    unsigned thr = s_prefix;
    int ties_needed = s_K;              // radix invariant
    int cgt = CAP - ties_needed;        // count strictly greater

    // unordered compaction for >thr (warp-aggregated atomics, no block syncs);
    // ties gathered into a small list for rank selection.
    unsigned lmask = (1u << lane) - 1u;
#pragma unroll
    for (int ch = 0; ch < 16; ch++) {
        int i = ch * 1024 + tid;
        unsigned v = u[i];
        int fgt = (v > thr);
        int fti = (v == thr);
        unsigned bg = __ballot_sync(0xffffffffu, fgt);
        if (bg) {
            int base = 0;
            if (lane == 0) base = atomicAdd(&s_gcnt, __popc(bg));
            base = __shfl_sync(0xffffffffu, base, 0);
            if (fgt) {
                int pos = base + __popc(bg & lmask);
                g_idx[e * CAP + pos] = i;
                g_vals[e * CAP + pos] = sc[i];
                if (do_counts) atomicAdd(&g_counts[i], 1.0f);
            }
        }
        unsigned bt = __ballot_sync(0xffffffffu, fti);
        if (bt) {
            int tb = 0;
            if (lane == 0) tb = atomicAdd(&s_tcnt, __popc(bt));
            tb = __shfl_sync(0xffffffffu, tb, 0);
            if (fti) {
                int tp = tb + __popc(bt & lmask);
                if (tp < TIE_CAP) s_tlist[tp] = i;
            }
        }
    }
    __syncthreads();
    int cti = s_tcnt;

    if (cti == ties_needed) {
        for (int j = tid; j < cti; j += 1024) {
            int i = s_tlist[j];
            int pos = cgt + j;
            g_idx[e * CAP + pos] = i;
            g_vals[e * CAP + pos] = sc[i];
            if (do_counts) atomicAdd(&g_counts[i], 1.0f);
        }
    } else if (cti <= TIE_CAP) {
        // keep the lowest-index ties (matches lax.top_k tie-break)
        for (int j = tid; j < cti; j += 1024) {
            int ii = s_tlist[j];
            int rank = 0;
            for (int q = 0; q < cti; q++) rank += (s_tlist[q] < ii);
            if (rank < ties_needed) {
                int pos = cgt + rank;
                g_idx[e * CAP + pos] = ii;
                g_vals[e * CAP + pos] = sc[ii];
                if (do_counts) atomicAdd(&g_counts[ii], 1.0f);
            }
        }
    } else {
        // degenerate fallback: ordered ballot-scan over all ties
        for (int ch = 0; ch < 16; ch++) {
            int i = ch * 1024 + tid;
            int fti = (u[i] == thr);
            unsigned bt = __ballot_sync(0xffffffffu, fti);
            if (lane == 0) wtot_ti[warp] = __popc(bt);
            __syncthreads();
            if (tid == 0) {
                int at = base_ti;
                for (int w = 0; w < 32; w++) {
                    int tt = wtot_ti[w];
                    wtot_ti[w] = at;
                    at += tt;
                }
                base_ti = at;
            }
            __syncthreads();
            int pt = wtot_ti[warp] + __popc(bt & lmask);
            if (fti && pt < ties_needed) {
                int pos = cgt + pt;
                g_idx[e * CAP + pos] = i;
                g_vals[e * CAP + pos] = sc[i];
                if (do_counts) atomicAdd(&g_counts[i], 1.0f);
            }
            __syncthreads();
        }
    }
}

// ---------------- expert GEMM: persistent grid + double-buffered smem ---------
// 304 blocks, 256 threads; tiles: 512 = e(8) x bm(16) x bn(4); 128x128x16
// tile, 8x8 micro via fma.rn.f32x2, ONE barrier per K-chunk, LDG->reg
// prefetch with end-of-chunk STS. Epilogue: packed vv-scale (mul.rn.f32x2)
// + vector red.global.add.v2.f32.  (R13 GEMM, byte-for-byte.)
__global__ void __launch_bounds__(256) k_gemm(const float* __restrict__ expert_w,
                                              int ctr_slot) {
    __shared__ __align__(16) float As[2][16][132];
    __shared__ __align__(16) float Bs[2][16][132];
    __shared__ int   s_rows[128];
    __shared__ float s_vals[128];
    __shared__ int   s_next;

    int tid = threadIdx.x;
    int tx = tid & 15, ty = tid >> 4;

    int am = tid & 127;
    int ah = (tid >> 7) * 8;                    // 0 or 8
    int bc = (tid & 31) * 4;
    int bk = tid >> 5;

    while (true) {
        __syncthreads();      // protects s_next, s_rows/s_vals, smem reuse
        if (tid == 0) s_next = atomicAdd(&g_tile_ctr[ctr_slot], 1);
        __syncthreads();
        int tile = s_next;
        if (tile >= N_TILES) break;

        int e  = tile >> 6;
        int bm = (tile >> 2) & 15;
        int bn = tile & 3;

        if (tid < 128) {
            s_rows[tid] = g_idx[e * CAP + bm * 128 + tid];
            s_vals[tid] = g_vals[e * CAP + bm * 128 + tid];
        }
        __syncthreads();

        const float* W = expert_w + (size_t)e * TWO_D * TWO_D + bn * 128;
        size_t arow = (size_t)s_rows[am] * TWO_D;

        // prologue: chunk 0 -> buffer 0
        {
            float4 a0 = *(const float4*)&g_x_eff[arow + ah];
            float4 a1 = *(const float4*)&g_x_eff[arow + ah + 4];
            float4 b0 = *(const float4*)&W[(size_t)bk * TWO_D + bc];
            float4 b1 = *(const float4*)&W[(size_t)(bk + 8) * TWO_D + bc];
            As[0][ah + 0][am] = a0.x; As[0][ah + 1][am] = a0.y;
            As[0][ah + 2][am] = a0.z; As[0][ah + 3][am] = a0.w;
            As[0][ah + 4][am] = a1.x; As[0][ah + 5][am] = a1.y;
            As[0][ah + 6][am] = a1.z; As[0][ah + 7][am] = a1.w;
            *(float4*)&Bs[0][bk][bc]     = b0;
            *(float4*)&Bs[0][bk + 8][bc] = b1;
        }
        __syncthreads();

        unsigned long long acc[8][4];
#pragma unroll
        for (int i = 0; i < 8; i++)
#pragma unroll
            for (int j = 0; j < 4; j++) acc[i][j] = 0ull;

#pragma unroll 1
        for (int c = 0; c < 32; c++) {
            int cur = c & 1, nxt = cur ^ 1;
            float4 pa0, pa1, pb0, pb1;
            bool more = (c + 1 < 32);
            if (more) {
                int kn = (c + 1) * 16;
                pa0 = *(const float4*)&g_x_eff[arow + kn + ah];
                pa1 = *(const float4*)&g_x_eff[arow + kn + ah + 4];
                pb0 = *(const float4*)&W[(size_t)(kn + bk) * TWO_D + bc];
                pb1 = *(const float4*)&W[(size_t)(kn + bk + 8) * TWO_D + bc];
            }

#pragma unroll
            for (int kk = 0; kk < 16; kk++) {
                float4 a0 = *(const float4*)&As[cur][kk][ty * 4];
                float4 a1 = *(const float4*)&As[cur][kk][ty * 4 + 64];
                ulonglong2 b0 = *(const ulonglong2*)&Bs[cur][kk][tx * 4];
                ulonglong2 b1 = *(const ulonglong2*)&Bs[cur][kk][tx * 4 + 64];
                float av[8] = {a0.x, a0.y, a0.z, a0.w, a1.x, a1.y, a1.z, a1.w};
#pragma unroll
                for (int i = 0; i < 8; i++) {
                    unsigned long long ad;
                    PACK2(ad, av[i]);
                    FMA2(acc[i][0], ad, b0.x);
                    FMA2(acc[i][1], ad, b0.y);
                    FMA2(acc[i][2], ad, b1.x);
                    FMA2(acc[i][3], ad, b1.y);
                }
            }

            if (more) {
                As[nxt][ah + 0][am] = pa0.x; As[nxt][ah + 1][am] = pa0.y;
                As[nxt][ah + 2][am] = pa0.z; As[nxt][ah + 3][am] = pa0.w;
                As[nxt][ah + 4][am] = pa1.x; As[nxt][ah + 5][am] = pa1.y;
                As[nxt][ah + 6][am] = pa1.z; As[nxt][ah + 7][am] = pa1.w;
                *(float4*)&Bs[nxt][bk][bc]     = pb0;
                *(float4*)&Bs[nxt][bk + 8][bc] = pb1;
                __syncthreads();   // stores to nxt visible; cur free for overwrite
            }
        }

#pragma unroll
        for (int i = 0; i < 8; i++) {
            int m = ty * 4 + (i & 3) + (i >> 2) * 64;
            int token = s_rows[m];
            unsigned long long vvd;
            PACK2(vvd, s_vals[m]);
            float* p = g_pred + (size_t)token * TWO_D + bn * 128;
#pragma unroll
            for (int jp = 0; jp < 4; jp++) {
                unsigned long long sc2;
                MUL2(sc2, acc[i][jp], vvd);
                float lo, hi;
                UNPACK2(lo, hi, sc2);
                int n = tx * 4 + (jp & 1) * 2 + (jp >> 1) * 64;
                red2(&p[n], lo, hi);
            }
        }
    }
}

// ---------------- state update (float4) ---------------------------------------
__global__ void k_update(float lr) {
    int i = blockIdx.x * blockDim.x + threadIdx.x;
    if (i >= NELEM / 4) return;
    float4 t = ((const float4*)g_x_target)[i];
    float4 p = ((const float4*)g_pred)[i];
    float4 s = ((float4*)g_x_states)[i];
    s.x += lr * fminf(fmaxf(t.x - p.x, -10.f), 10.f);
    s.y += lr * fminf(fmaxf(t.y - p.y, -10.f), 10.f);
    s.z += lr * fminf(fmaxf(t.z - p.z, -10.f), 10.f);
    s.w += lr * fminf(fmaxf(t.w - p.w, -10.f), 10.f);
    ((float4*)g_x_states)[i] = s;
}

// ---------------- normalize + tanh activate (float4) ---------------------------
__global__ void k_activate(const float* __restrict__ act_bias) {
    int i = blockIdx.x * blockDim.x + threadIdx.x;
    if (i >= NELEM / 4) return;
    int n = i >> 7;            // 128 float4 per token row
    int q = i & 127;           // covers d = 2q, 2q+1
    float dn = fmaxf(g_counts[n], 1.0f);
    float inv = 1.0f / dn;
    float4 p = ((const float4*)g_pred)[i];
    float4 b = ((const float4*)act_bias)[q];
    float4 r;
    r.x = tanhf(p.x * inv + b.x);
    r.y = tanhf(p.y * inv + b.y);
    r.z = tanhf(p.z * inv + b.z);
    r.w = tanhf(p.w * inv + b.w);
    ((float4*)g_x_states)[i] = r;
}

// ---------------- final output + residual norm (float4) ------------------------
__global__ void k_output(float* __restrict__ out) {
    __shared__ double sd[256];
    int tid = threadIdx.x;
    int i = blockIdx.x * blockDim.x + tid;
    double sloc = 0.0;
    if (i < NELEM / 4) {
        float4 xs = ((const float4*)g_x_states)[i];
        float4 tg = ((const float4*)g_x_target)[i];
        float4 pg = ((const float4*)g_pred)[i];
        float4 o;
        o.x = xs.x + 0.5f * (tg.x - pg.x);
        o.y = xs.y + 0.5f * (tg.y - pg.y);
        o.z = xs.z + 0.5f * (tg.z - pg.z);
        o.w = xs.w + 0.5f * (tg.w - pg.w);
        ((float4*)out)[i] = o;
        float d0r = tg.x - pg.x, d0i = tg.y - pg.y;
        float d1r = tg.z - pg.z, d1i = tg.w - pg.w;
        sloc = (double)sqrtf(d0r * d0r + d0i * d0i) + (double)sqrtf(d1r * d1r + d1i * d1i);
    }
    sd[tid] = sloc;
    __syncthreads();
    for (int s = 128; s > 0; s >>= 1) {
        if (tid < s) sd[tid] += sd[tid + s];
        __syncthreads();
    }
    if (tid == 0) atomicAdd(&g_resnorm, sd[0]);
}

__global__ void k_final(float* __restrict__ out, int pos) {
    out[pos] = (float)(g_resnorm / (double)NPAIR);
}

// ---------------- host launcher -----------------------------------------------
extern "C" void kernel_launch(void* const* d_in, const int* in_sizes, int n_in,
                              void* d_out, int out_size) {
    const float* x        = (const float*)d_in[0];
    const float* dgains   = (const float*)d_in[1];
    const float* cosp     = (const float*)d_in[2];
    const float* sinp     = (const float*)d_in[3];
    const float* gate_w   = (const float*)d_in[4];
    const float* expert_w = (const float*)d_in[5];
    const float* act_bias = (const float*)d_in[6];
    float* out = (float*)d_out;

    cudaFuncSetAttribute(k_topk, cudaFuncAttributeMaxDynamicSharedMemorySize, 64 * 1024);

    const int EB = 256;

    k_init<<<(NPAIR + EB - 1) / EB, EB>>>(x, cosp, sinp);

    float lr = 0.5f;
    int slot = 0;
    for (int it = 0; it < 8; it++) {
        k_delays_gate<<<N_TOK / 8, 512>>>(dgains, gate_w);
        k_topk<<<E_, 1024, 64 * 1024>>>(it == 7 ? 1 : 0);
        k_gemm<<<GEMM_BLOCKS, 256>>>(expert_w, slot++);
        if (it < 7) {
            k_update<<<NELEM / 4 / EB, EB>>>(lr);
            lr *= 0.85f;
        }
    }

    k_activate<<<NELEM / 4 / EB, EB>>>(act_bias);

    // gradient pass
    k_delays_gate<<<N_TOK / 8, 512>>>(dgains, gate_w);
    k_topk<<<E_, 1024, 64 * 1024>>>(0);
    k_gemm<<<GEMM_BLOCKS, 256>>>(expert_w, slot++);

    k_output<<<NELEM / 4 / EB, EB>>>(out);
    k_final<<<1, 1>>>(out, out_size - 1);
}